// round 2
// baseline (speedup 1.0000x reference)
#include <cuda_runtime.h>
#include <math.h>

#define SS 7
#define NCLS 20
#define ROWS_PER_BLOCK 128
#define NROW_TOTAL (8192 * 7 * 7)
#define NBLOCKS (NROW_TOTAL / ROWS_PER_BLOCK)   // 3136 exactly

// scratch accumulators:
// 0 contain_num, 1 obj_num, 2 notcontain_num, 3 noobj_num,
// 4 cls_num, 5 sum_iou, 6 acc, 7 n_obj
__device__ double g_sums[8];

__global__ void zero_kernel() {
    if (threadIdx.x < 8) g_sums[threadIdx.x] = 0.0;
}

__global__ void __launch_bounds__(ROWS_PER_BLOCK)
loss_main_kernel(const float* __restrict__ out, const float* __restrict__ tgt) {
    __shared__ float s_out[ROWS_PER_BLOCK * 30];
    __shared__ float s_tgt[ROWS_PER_BLOCK * 30];

    const int t = threadIdx.x;
    const size_t base = (size_t)blockIdx.x * (ROWS_PER_BLOCK * 30);

    // Stage the block's contiguous chunk via float4 (base offset 15360*blockIdx bytes, 16B aligned)
    const float4* o4 = (const float4*)(out + base);
    const float4* t4 = (const float4*)(tgt + base);
    float4* so4 = (float4*)s_out;
    float4* st4 = (float4*)s_tgt;
    constexpr int NV4 = ROWS_PER_BLOCK * 30 / 4;  // 960
#pragma unroll
    for (int i = t; i < NV4; i += ROWS_PER_BLOCK) {
        so4[i] = o4[i];
        st4[i] = t4[i];
    }
    __syncthreads();

    const float* o = s_out + t * 30;
    const float* g = s_tgt + t * 30;

    const float m = (g[4] > 0.0f) ? 1.0f : 0.0f;

    const float inv_s = 1.0f / (float)SS;

    // target box corners
    const float tx0 = g[0] * inv_s - 0.5f * g[2];
    const float ty0 = g[1] * inv_s - 0.5f * g[3];
    const float tx1 = g[0] * inv_s + 0.5f * g[2];
    const float ty1 = g[1] * inv_s + 0.5f * g[3];
    const float at  = (tx1 - tx0) * (ty1 - ty0);

    float iou[2];
#pragma unroll
    for (int b = 0; b < 2; b++) {
        const float* pb = o + b * 5;
        const float px0 = pb[0] * inv_s - 0.5f * pb[2];
        const float py0 = pb[1] * inv_s - 0.5f * pb[3];
        const float px1 = pb[0] * inv_s + 0.5f * pb[2];
        const float py1 = pb[1] * inv_s + 0.5f * pb[3];
        const float ap  = (px1 - px0) * (py1 - py0);
        const float ulx = fmaxf(px0, tx0);
        const float uly = fmaxf(py0, ty0);
        const float lrx = fminf(px1, tx1);
        const float lry = fminf(py1, ty1);
        const float wi  = fmaxf(lrx - ulx, 0.0f);
        const float hi  = fmaxf(lry - uly, 0.0f);
        const float inter = wi * hi;
        iou[b] = inter / (ap + at - inter);
    }

    // argmax ties -> first index, so box 1 wins only on strict >
    const int resp = (iou[1] > iou[0]) ? 1 : 0;
    const float max_iou = fmaxf(iou[0], iou[1]);
    const float min_iou = fminf(iou[0], iou[1]);

    const float* rb = o + resp * 5;
    const float* nb = o + (1 - resp) * 5;

    float dx = rb[0] - g[0];
    float dy = rb[1] - g[1];
    float dw = sqrtf(rb[2]) - sqrtf(g[2]);
    float dh = sqrtf(rb[3]) - sqrtf(g[3]);
    const float contain = dx * dx + dy * dy + dw * dw + dh * dh;

    const float d_obj = rb[4] - max_iou;
    const float objl  = d_obj * d_obj;
    const float notc  = nb[4] * nb[4];

    const float dn0 = o[4] - g[4];
    const float dn1 = o[9] - g[9];
    const float noobj = dn0 * dn0 + dn1 * dn1;

    float cls = 0.0f;
    int pa = 0, ta = 0;
    float pbest = o[10], tbest = g[10];
#pragma unroll
    for (int k = 0; k < NCLS; k++) {
        const float po = o[10 + k];
        const float tg = g[10 + k];
        const float d = po - tg;
        cls += d * d;
        if (po > pbest) { pbest = po; pa = k; }
        if (tg > tbest) { tbest = tg; ta = k; }
    }
    const float accv = (m > 0.0f && pa == ta) ? 1.0f : 0.0f;

    float vals[8];
    vals[0] = m * contain;
    vals[1] = m * objl;
    vals[2] = m * notc;
    vals[3] = (1.0f - m) * noobj;
    vals[4] = m * cls;
    vals[5] = m * min_iou;
    vals[6] = accv;
    vals[7] = m;

    // warp reduce
#pragma unroll
    for (int off = 16; off > 0; off >>= 1) {
#pragma unroll
        for (int j = 0; j < 8; j++)
            vals[j] += __shfl_down_sync(0xFFFFFFFFu, vals[j], off);
    }

    __shared__ float s_red[4][8];
    const int warp = t >> 5;
    const int lane = t & 31;
    if (lane == 0) {
#pragma unroll
        for (int j = 0; j < 8; j++) s_red[warp][j] = vals[j];
    }
    __syncthreads();

    if (warp == 0 && lane < 8) {
        float s = s_red[0][lane] + s_red[1][lane] + s_red[2][lane] + s_red[3][lane];
        atomicAdd(&g_sums[lane], (double)s);
    }
}

__global__ void finalize_kernel(float* __restrict__ outp) {
    const double n_obj   = g_sums[7];
    const double n_noobj = (double)NROW_TOTAL - n_obj;

    const double contain    = g_sums[0] / (2.0 * n_obj);
    const double obj_loss   = g_sums[1] / n_obj;
    const double not_cont   = g_sums[2] / n_obj;
    const double noobj_loss = g_sums[3] / (2.0 * n_noobj);
    const double cls_loss   = g_sums[4] / (n_obj * (double)NCLS);

    const double loss = 5.0 * contain + obj_loss + 0.5 * (noobj_loss + not_cont) + cls_loss;

    outp[0] = (float)loss;
    outp[1] = (float)g_sums[5];
    outp[2] = (float)g_sums[6];
}

extern "C" void kernel_launch(void* const* d_in, const int* in_sizes, int n_in,
                              void* d_out, int out_size) {
    const float* out_t = (const float*)d_in[0];
    const float* tgt_t = (const float*)d_in[1];
    float* res = (float*)d_out;

    zero_kernel<<<1, 32>>>();
    loss_main_kernel<<<NBLOCKS, ROWS_PER_BLOCK>>>(out_t, tgt_t);
    finalize_kernel<<<1, 1>>>(res);
}